// round 1
// baseline (speedup 1.0000x reference)
#include <cuda_runtime.h>
#include <math.h>

// Problem constants (fixed by setup_inputs)
#define Bc   4
#define Ec   16
#define Cc   24
#define HWc  262144            // 512*512
#define TILE 4096              // pixels per pass-1 block

#define DELTA_VAR  0.75f
#define DELTA_DIST 2.0f
#define ALPHA_W 1.0f
#define BETA_W  1.0f
#define GAMMA_W 0.001f

// ---------------- device scratch (no allocation allowed) ----------------
__device__ float g_sum[Bc * Cc * Ec];   // [b][c][e] cluster embedding sums
__device__ float g_cnt[Bc * Cc];        // [b][c]    pixel counts
__device__ float g_hinge[Bc * Cc];      // [b][c]    hinged variance sums

// ---------------- kernel 0: zero scratch ----------------
__global__ void k_zero() {
    int i = blockIdx.x * blockDim.x + threadIdx.x;
    if (i < Bc * Cc * Ec) g_sum[i] = 0.f;
    if (i < Bc * Cc) { g_cnt[i] = 0.f; g_hinge[i] = 0.f; }
}

// ---------------- kernel 1: per-(b,c) sums + counts ----------------
// Block = 256 threads organized as 16(e) x 16(j). Thread (e,j) privately owns
// shared column e*16+j of acc[C][E][16]  -> bank == lane, conflict-free RMW,
// no atomics in the hot loop. Labels staged once per tile, reused for all 16 e.
__global__ void __launch_bounds__(256)
k_sums(const float* __restrict__ input, const int* __restrict__ target) {
    __shared__ float  acc[Cc * 256];     // [c][e*16+j]  24 KB
    __shared__ uchar4 lab4[TILE / 4];    // 4 KB of labels (values 0..23)
    __shared__ int    hist[Cc];

    const int tid   = threadIdx.x;
    const int b     = blockIdx.y;
    const int tile0 = blockIdx.x * TILE;

    #pragma unroll
    for (int i = tid; i < Cc * 256; i += 256) acc[i] = 0.f;
    if (tid < Cc) hist[tid] = 0;
    __syncthreads();

    // stage labels (coalesced int4 loads) + histogram (few shared atomics)
    const int4* tgt4 = (const int4*)(target + b * HWc + tile0);
    #pragma unroll
    for (int i = tid; i < TILE / 4; i += 256) {
        int4 l = tgt4[i];
        lab4[i] = make_uchar4((unsigned char)l.x, (unsigned char)l.y,
                              (unsigned char)l.z, (unsigned char)l.w);
        atomicAdd(&hist[l.x], 1); atomicAdd(&hist[l.y], 1);
        atomicAdd(&hist[l.z], 1); atomicAdd(&hist[l.w], 1);
    }
    __syncthreads();

    const int e = tid >> 4;
    const int j = tid & 15;
    const float4* src =
        (const float4*)(input + (size_t)b * Ec * HWc + (size_t)e * HWc + tile0);
    float* accej = acc + e * 16 + j;     // column base; index lbl*256

    #pragma unroll 8
    for (int k = 0; k < TILE / 64; ++k) {
        float4 v = src[k * 16 + j];              // pixels k*64 + j*4 .. +3
        uchar4 l = lab4[k * 16 + j];
        accej[(int)l.x * 256] += v.x;
        accej[(int)l.y * 256] += v.y;
        accej[(int)l.z * 256] += v.z;
        accej[(int)l.w * 256] += v.w;
    }
    __syncthreads();

    // reduce over j (16 columns) once per block, then global accumulate
    for (int o = tid; o < Cc * Ec; o += 256) {   // o = c*16 + e
        float s = 0.f;
        #pragma unroll
        for (int jj = 0; jj < 16; ++jj) s += acc[o * 16 + jj];
        atomicAdd(&g_sum[b * Cc * Ec + o], s);
    }
    if (tid < Cc) atomicAdd(&g_cnt[b * Cc + tid], (float)hist[tid]);
}

// ---------------- kernel 2: hinged variance per pixel ----------------
// Each thread handles 4 consecutive pixels; 16 independent LDG.128 per group.
__global__ void __launch_bounds__(256)
k_var(const float* __restrict__ input, const int* __restrict__ target) {
    __shared__ float mu_t[Ec * Cc];   // transposed [e][c]: conflict-free lookups
    __shared__ float hsum[Cc];

    const int tid = threadIdx.x;
    const int b   = blockIdx.y;

    if (tid < Cc) hsum[tid] = 0.f;
    for (int i = tid; i < Cc * Ec; i += 256) {   // i = c*16 + e
        int c = i >> 4, e = i & 15;
        mu_t[e * Cc + c] = g_sum[b * Cc * Ec + i] / g_cnt[b * Cc + c];
    }
    __syncthreads();

    const int p4 = (blockIdx.x * 256 + tid) * 4;
    const int4 l = *(const int4*)(target + b * HWc + p4);
    const float* base = input + (size_t)b * Ec * HWc + p4;

    float s0 = 0.f, s1 = 0.f, s2 = 0.f, s3 = 0.f;
    #pragma unroll
    for (int e = 0; e < Ec; ++e) {
        float4 v = *(const float4*)(base + (size_t)e * HWc);
        const float* m = mu_t + e * Cc;
        float d0 = v.x - m[l.x]; s0 += d0 * d0;
        float d1 = v.y - m[l.y]; s1 += d1 * d1;
        float d2 = v.z - m[l.z]; s2 += d2 * d2;
        float d3 = v.w - m[l.w]; s3 += d3 * d3;
    }
    float h0 = fmaxf(sqrtf(s0) - DELTA_VAR, 0.f); h0 *= h0;
    float h1 = fmaxf(sqrtf(s1) - DELTA_VAR, 0.f); h1 *= h1;
    float h2 = fmaxf(sqrtf(s2) - DELTA_VAR, 0.f); h2 *= h2;
    float h3 = fmaxf(sqrtf(s3) - DELTA_VAR, 0.f); h3 *= h3;

    atomicAdd(&hsum[l.x], h0);
    atomicAdd(&hsum[l.y], h1);
    atomicAdd(&hsum[l.z], h2);
    atomicAdd(&hsum[l.w], h3);
    __syncthreads();
    if (tid < Cc) atomicAdd(&g_hinge[b * Cc + tid], hsum[tid]);
}

// ---------------- kernel 3: finalize (variance + distance + reg) ----------------
__global__ void __launch_bounds__(256)
k_final(float* __restrict__ out) {
    __shared__ float mu[Bc * Cc * Ec];   // [b][c][e]
    __shared__ float red[256];

    const int tid = threadIdx.x;
    for (int i = tid; i < Bc * Cc * Ec; i += 256) {
        int bc = i >> 4;                 // b*Cc + c
        mu[i] = g_sum[i] / g_cnt[bc];
    }
    __syncthreads();

    float acc = 0.f;

    // variance term + reg term: one entry per (b,c)
    for (int i = tid; i < Bc * Cc; i += 256) {
        float varc = g_hinge[i] / g_cnt[i];
        float nsq = 0.f;
        #pragma unroll
        for (int e = 0; e < Ec; ++e) { float m = mu[i * 16 + e]; nsq += m * m; }
        float regc = (nsq == 0.f) ? 0.f : sqrtf(nsq);
        acc += (ALPHA_W * varc + GAMMA_W * regc) * (1.0f / (Cc * Bc));
    }

    // distance term: all ordered pairs (ci != cj)
    for (int t = tid; t < Bc * Cc * Cc; t += 256) {
        int b  = t / (Cc * Cc);
        int rc = t - b * (Cc * Cc);
        int ci = rc / Cc, cj = rc - ci * Cc;
        if (ci != cj) {
            const float* a = mu + (b * Cc + ci) * 16;
            const float* c = mu + (b * Cc + cj) * 16;
            float s = 0.f;
            #pragma unroll
            for (int e = 0; e < Ec; ++e) { float d = a[e] - c[e]; s += d * d; }
            float dist = (s == 0.f) ? 0.f : sqrtf(s);
            float hd = fmaxf(2.0f * DELTA_DIST - dist, 0.f);
            acc += BETA_W * hd * hd * (1.0f / ((float)Bc * Cc * (Cc - 1)));
        }
    }

    red[tid] = acc;
    __syncthreads();
    #pragma unroll
    for (int s = 128; s > 0; s >>= 1) {
        if (tid < s) red[tid] += red[tid + s];
        __syncthreads();
    }
    if (tid == 0) out[0] = red[0];
}

// ---------------- launch ----------------
extern "C" void kernel_launch(void* const* d_in, const int* in_sizes, int n_in,
                              void* d_out, int out_size) {
    const float* input  = (const float*)d_in[0];
    const int*   target = (const int*)d_in[1];
    float*       out    = (float*)d_out;

    k_zero<<<(Bc * Cc * Ec + 255) / 256, 256>>>();

    dim3 g1(HWc / TILE, Bc);           // 64 x 4 blocks
    k_sums<<<g1, 256>>>(input, target);

    dim3 g2(HWc / 1024, Bc);           // 256 x 4 blocks
    k_var<<<g2, 256>>>(input, target);

    k_final<<<1, 256>>>(out);
}